// round 9
// baseline (speedup 1.0000x reference)
#include <cuda_runtime.h>
#include <cstdint>
#include <math.h>

#define NN     4096
#define HDIM   256
#define HEADS  4
#define HD     64
#define EC     131072
#define TOPK   15
#define CAP    160
#define RT     512      // k_row block threads
#define GROUPS 2        // row-groups per block
#define GT     256      // threads per group
#define RPT    16       // candidates per thread = NN / GT
#define ECAP   96       // per-row edge list in smem (Poisson(32); +11 sigma)
#define BUFSZ  256
#define GRID   296      // 2 blocks/SM
#define FULLM  0xffffffffu

// ---------------- device scratch ----------------
__device__ float2 g_vd[HEADS][HDIM];
__device__ float2 g_vs[HEADS][HDIM];
__device__ float4 g_sd[NN];
__device__ float4 g_ss[NN];
__device__ float  g_badj[NN];            // act_j ? 0.15*sum(ss_j) : -inf
__device__ int    g_cur[NN];
__device__ ulonglong2 g_edge[NN * CAP];  // .x = (pos<<32)|float_bits(w), .y = col
__device__ int    g_is_byte;

// ---------------- k_row shared layout ----------------
struct GroupSmem {
    unsigned long long buf[BUFSZ];   // candidate buffer
    unsigned long long sel[TOPK];
    float   ewt[ECAP];
    int     ecol[ECAP];
    int     epos[ECAP];
    int     hist1[256];
    int     hist2[256];
    uint8_t idx8[NN];                // corr winner index+1 per column (0 = none)
    int     ncand, B1, above1, B2, above2;
};
struct RowSmem {
    float4 ss[NN];                   // 64 KB
    float  badj[NN];                 // 16 KB
    GroupSmem grp[GROUPS];           // ~19 KB
};

#define BARG(gid) asm volatile("bar.sync %0, %1;" :: "r"((gid) + 1), "r"(GT) : "memory")

// ---------------- double-single helpers ----------------
__device__ __forceinline__ void dsadd(float& s, float& c, float p, float pe) {
    float t = s + p;
    float z = t - s;
    float e = (s - (t - z)) + (p - z);
    s = t;
    c += e + pe;
}

// ---------------- L1: detect bool width + zero counters + fold ----------------
__global__ __launch_bounds__(256) void k_setup(const unsigned* __restrict__ mask_words,
                                               const float* __restrict__ W,
                                               const float* __restrict__ att) {
    int b = blockIdx.x, tid = threadIdx.x;
    if (b == 0) {
        __shared__ int s_byte;
        if (tid == 0) s_byte = 0;
        __syncthreads();
        for (int t = tid; t < 4096; t += 256) {
            unsigned w = mask_words[t];
            if (w > 1u) {
                unsigned b0 = w & 0xFF, b1 = (w >> 8) & 0xFF,
                         b2 = (w >> 16) & 0xFF, b3 = w >> 24;
                if (b0 <= 1u && b1 <= 1u && b2 <= 1u && b3 <= 1u) s_byte = 1;
            }
        }
        __syncthreads();
        if (tid == 0) g_is_byte = s_byte;
    } else if (b <= 16) {
        g_cur[(b - 1) * 256 + tid] = 0;
    } else {
        int h = b - 17;
        int k = tid;
        float sd = 0.f, cd = 0.f, ss = 0.f, cs = 0.f;
        #pragma unroll 8
        for (int dd = 0; dd < HD; dd++) {
            float w   = W[(h * HD + dd) * HDIM + k];
            float ad  = att[h * 2 * HD + dd];
            float as_ = att[h * 2 * HD + HD + dd];
            float p = ad * w;  float pe = fmaf(ad, w, -p);
            dsadd(sd, cd, p, pe);
            p = as_ * w;       pe = fmaf(as_, w, -p);
            dsadd(ss, cs, p, pe);
        }
        float hi = sd + cd;
        g_vd[h][k] = make_float2(hi, (sd - hi) + cd);
        hi = ss + cs;
        g_vs[h][k] = make_float2(hi, (ss - hi) + cs);
    }
}

// ---------------- L2: sds + edge scatter ----------------
__global__ __launch_bounds__(1024) void k_mid(const float* __restrict__ E,
                                              const int* __restrict__ eidx,
                                              const float* __restrict__ ew,
                                              const uint8_t* __restrict__ act) {
    int b = blockIdx.x;
    if (b < 128) {
        int wid = threadIdx.x >> 5;
        int lane = threadIdx.x & 31;
        int g = b * 32 + wid;
        const float* er = E + (size_t)g * HDIM;
        float s[8], c[8];
        #pragma unroll
        for (int a = 0; a < 8; a++) { s[a] = 0.f; c[a] = 0.f; }
        for (int k = lane; k < HDIM; k += 32) {
            float e = er[k];
            #pragma unroll
            for (int h = 0; h < HEADS; h++) {
                float2 v = g_vd[h][k];
                float p = e * v.x;
                float pe = fmaf(e, v.x, -p);
                pe = fmaf(e, v.y, pe);
                dsadd(s[h], c[h], p, pe);
                v = g_vs[h][k];
                p = e * v.x;
                pe = fmaf(e, v.x, -p);
                pe = fmaf(e, v.y, pe);
                dsadd(s[4 + h], c[4 + h], p, pe);
            }
        }
        #pragma unroll
        for (int off = 16; off; off >>= 1) {
            #pragma unroll
            for (int a = 0; a < 8; a++) {
                float os = __shfl_down_sync(FULLM, s[a], off);
                float oc = __shfl_down_sync(FULLM, c[a], off);
                float t = s[a] + os;
                float z = t - s[a];
                c[a] += oc + ((s[a] - (t - z)) + (os - z));
                s[a] = t;
            }
        }
        if (lane == 0) {
            g_sd[g] = make_float4(s[0] + c[0], s[1] + c[1], s[2] + c[2], s[3] + c[3]);
            float t0 = s[4] + c[4], t1 = s[5] + c[5], t2 = s[6] + c[6], t3 = s[7] + c[7];
            g_ss[g] = make_float4(t0, t1, t2, t3);
            bool aj = g_is_byte ? (act[g] != 0) : (((const unsigned*)act)[g] != 0u);
            g_badj[g] = aj ? 0.15f * ((t0 + t1) + (t2 + t3)) : -INFINITY;
        }
    } else {
        int e = (b - 128) * 1024 + threadIdx.x;
        if (e < EC) {
            int r = eidx[e];
            int cc = eidx[EC + e];
            int p = atomicAdd(&g_cur[r], 1);
            if (p < CAP) {
                ulonglong2 rec;
                rec.x = ((unsigned long long)(unsigned)e << 32) |
                        (unsigned long long)__float_as_uint(ew[e]);
                rec.y = (unsigned long long)(unsigned)cc;
                g_edge[r * CAP + p] = rec;
            }
        }
    }
}

// warp-collective (one warp): largest bin B with suffix-count >= K
__device__ __forceinline__ void scan_hist(const int* __restrict__ hist, int K,
                                          int* outB, int* outAbove) {
    int lane = threadIdx.x & 31;
    int base = lane * 8;
    int h[8];
    #pragma unroll
    for (int r = 0; r < 8; r++) h[r] = hist[base + r];
    int ls[8];
    int s = 0;
    #pragma unroll
    for (int r = 7; r >= 0; r--) { s += h[r]; ls[r] = s; }
    int run = s;
    #pragma unroll
    for (int off = 1; off < 32; off <<= 1) {
        int t = __shfl_down_sync(FULLM, run, off);
        if (lane + off < 32) run += t;
    }
    int above = run - s;
    int cand = -1, candAbove = 0;
    #pragma unroll
    for (int r = 7; r >= 0; r--) {
        if (cand < 0 && above + ls[r] >= K) {
            cand = base + r;
            candAbove = above + ls[r] - h[r];
        }
    }
    int bestB = cand, bestA = candAbove;
    #pragma unroll
    for (int off = 16; off; off >>= 1) {
        int ob = __shfl_xor_sync(FULLM, bestB, off);
        int oa = __shfl_xor_sync(FULLM, bestA, off);
        if (ob > bestB) { bestB = ob; bestA = oa; }
    }
    if (lane == 0) {
        *outB = (bestB < 0) ? 0 : bestB;
        *outAbove = (bestB < 0) ? 0 : bestA;
    }
}

// ---------------- L3: 2 independent 256-thread row-groups per block -----------
__global__ __launch_bounds__(RT) void k_row(const uint8_t* __restrict__ mask,
                                            const uint8_t* __restrict__ act,
                                            const float* __restrict__ lambda_p,
                                            float* __restrict__ out) {
    extern __shared__ RowSmem sm[];
    RowSmem* S = sm;

    const int tid = threadIdx.x;
    const int g   = tid >> 8;          // group 0/1
    const int gt  = tid & (GT - 1);    // thread in group
    const int lane = tid & 31;
    const int wg  = gt >> 5;           // warp in group
    GroupSmem& G = S->grp[g];

    // ---- block prologue ----
    #pragma unroll
    for (int k = 0; k < 8; k++) {
        int j = tid + k * RT;
        S->ss[j] = __ldg(&g_ss[j]);
        S->badj[j] = __ldg(&g_badj[j]);
    }
    {
        unsigned* idxw = (unsigned*)G.idx8;
        #pragma unroll
        for (int r = 0; r < 4; r++) idxw[gt + r * GT] = 0u;
    }
    const float lam = __ldg(lambda_p);
    const int is_byte = g_is_byte;
    __syncthreads();                   // only block-wide barrier

    for (int i = blockIdx.x * GROUPS + g; i < NN; i += GRID * GROUPS) {
        // ---- A: per-row init + edge list load ----
        G.hist1[gt] = 0;
        G.hist2[gt] = 0;
        if (gt == 0) G.ncand = 0;
        if (gt < TOPK) G.sel[gt] = 0ULL;
        int cnt = g_cur[i];
        if (cnt > ECAP) cnt = ECAP;
        if (gt < cnt) {
            ulonglong2 rec = __ldg(&g_edge[i * CAP + gt]);
            G.ecol[gt] = (int)rec.y;
            G.epos[gt] = (int)(rec.x >> 32);
            G.ewt[gt]  = __uint_as_float((unsigned)rec.x);
        }
        BARG(g);

        // ---- B: last-write-wins resolve; winners write idx table ----
        if (gt < cnt) {
            int c = G.ecol[gt], p = G.epos[gt];
            bool win = true;
            for (int s = 0; s < cnt; s++)
                if (G.ecol[s] == c && G.epos[s] > p) win = false;
            if (win) G.idx8[c] = (uint8_t)(gt + 1);
        }
        BARG(g);

        // ---- C: compute 16 keys + level-1 histogram ----
        const float4 sdi = __ldg(&g_sd[i]);
        const float ci = 0.15f * ((sdi.x + sdi.y) + (sdi.z + sdi.w));
        const uint8_t*  mrow8  = mask + (size_t)i * NN;
        const unsigned* mrow32 = (const unsigned*)mask + (size_t)i * NN;
        const bool acti = is_byte ? (act[i] != 0) : (((const unsigned*)act)[i] != 0u);

        unsigned kk[RPT];
        #pragma unroll
        for (int k = 0; k < RPT; k++) {
            int j = gt + k * GT;
            float4 ssj = S->ss[j];
            float x0 = sdi.x + ssj.x;
            float x1 = sdi.y + ssj.y;
            float x2 = sdi.z + ssj.z;
            float x3 = sdi.w + ssj.w;
            float sa = fabsf(x0) + fabsf(x1);
            float sb = fabsf(x2) + fabsf(x3);
            int e8 = (int)G.idx8[j];
            float w = e8 ? G.ewt[e8 - 1] : 0.0f;
            float a = S->badj[j];
            bool mj = is_byte ? (mrow8[j] != 0) : (mrow32[j] != 0u);
            float sc = ci + fmaf(lam, w, a);
            sc = fmaf(0.1f, sa + sb, sc);
            sc = (acti && mj) ? sc : -INFINITY;
            unsigned u = __float_as_uint(sc);
            u ^= ((unsigned)(((int)u) >> 31)) | 0x80000000u;
            kk[k] = u;
        }
        #pragma unroll
        for (int k = 0; k < RPT; k++) {
            unsigned b1 = kk[k] >> 24;
            unsigned peers = __match_any_sync(FULLM, b1);
            if ((peers & ((1u << lane) - 1u)) == 0)
                atomicAdd(&G.hist1[b1], (int)__popc(peers));
        }
        BARG(g);

        // ---- D: level-1 scan (group warp 0) ----
        if (wg == 0) scan_hist(G.hist1, TOPK, &G.B1, &G.above1);
        BARG(g);
        const int B1 = G.B1;
        const int above1 = G.above1;

        // ---- E: level-2 histogram within bin B1 ----
        #pragma unroll
        for (int k = 0; k < RPT; k++) {
            if ((int)(kk[k] >> 24) == B1)
                atomicAdd(&G.hist2[(kk[k] >> 16) & 0xFF], 1);
        }
        BARG(g);

        // ---- F: level-2 scan ----
        if (wg == 0) scan_hist(G.hist2, TOPK - above1, &G.B2, &G.above2);
        BARG(g);
        const int B2 = G.B2;

        // ---- G: append candidates above threshold ----
        #pragma unroll
        for (int k = 0; k < RPT; k++) {
            int b1k = (int)(kk[k] >> 24);
            bool cand = (b1k > B1) || (b1k == B1 && (int)((kk[k] >> 16) & 0xFF) >= B2);
            if (cand) {
                int p = atomicAdd(&G.ncand, 1);
                if (p < BUFSZ) {
                    int j = gt + k * GT;
                    G.buf[p] = ((unsigned long long)kk[k] << 32) |
                               (unsigned long long)(0xFFFFFFFFu - (unsigned)j);
                }
            }
        }
        BARG(g);

        // ---- H: rank-select top-15 ----
        int n = G.ncand < BUFSZ ? G.ncand : BUFSZ;
        {
            unsigned long long K = (gt < n) ? G.buf[gt] : 0ULL;
            int rank = 0;
            for (int s = 0; s < n; s++) rank += (G.buf[s] > K);
            if (gt < n && rank < TOPK) G.sel[rank] = K;
        }
        BARG(g);

        // ---- I: warp0 -> decode+softmax+write; warps 4..7 -> un-scatter idx ----
        if (wg == 0) {
            unsigned long long k64 = (lane < TOPK) ? G.sel[lane] : 0ULL;
            unsigned u = (unsigned)(k64 >> 32);
            float v = (u & 0x80000000u) ? __uint_as_float(u ^ 0x80000000u)
                                        : __uint_as_float(~u);
            unsigned j = 0xFFFFFFFFu - (unsigned)(k64 & 0xFFFFFFFFu);
            float v0 = __shfl_sync(FULLM, v, 0);
            float e = (lane < TOPK) ? expf(v - v0) : 0.f;
            float s = e;
            #pragma unroll
            for (int off = 16; off; off >>= 1) s += __shfl_xor_sync(FULLM, s, off);
            if (lane < TOPK) {
                out[(size_t)i * TOPK + lane] = (float)j;
                out[(size_t)NN * TOPK + (size_t)i * TOPK + lane] = (float)i;
                out[2 * (size_t)NN * TOPK + (size_t)i * TOPK + lane] = e / s;
            }
        } else if (gt >= 128) {
            int t2 = gt - 128;
            if (t2 < cnt) G.idx8[G.ecol[t2]] = 0;
        }
        BARG(g);
    }
}

// ---------------- launcher ----------------
extern "C" void kernel_launch(void* const* d_in, const int* in_sizes, int n_in,
                              void* d_out, int out_size) {
    const float*   emb  = (const float*)d_in[0];
    const float*   W    = (const float*)d_in[1];
    const float*   att  = (const float*)d_in[2];
    const float*   lam  = (const float*)d_in[3];
    const uint8_t* mask = (const uint8_t*)d_in[4];
    const uint8_t* act  = (const uint8_t*)d_in[5];
    const int*     eidx = (const int*)d_in[6];
    const float*   ew   = (const float*)d_in[7];
    float* out = (float*)d_out;

    cudaFuncSetAttribute(k_row, cudaFuncAttributeMaxDynamicSharedMemorySize,
                         (int)sizeof(RowSmem));

    k_setup<<<21, 256>>>((const unsigned*)mask, W, att);
    k_mid<<<256, 1024>>>(emb, eidx, ew, act);
    k_row<<<GRID, RT, sizeof(RowSmem)>>>(mask, act, lam, out);
}

// round 10
// speedup vs baseline: 1.1476x; 1.1476x over previous
#include <cuda_runtime.h>
#include <cstdint>
#include <math.h>

#define NN     4096
#define HDIM   256
#define HEADS  4
#define HD     64
#define EC     131072
#define TOPK   15
#define CAP    160
#define RT     512
#define CPT    8
#define BUFSZ  256
#define GRID   296      // exactly 2 blocks/SM on 148 SMs -> all co-resident
#define FULLM  0xffffffffu

// ---------------- device scratch ----------------
__device__ float2 g_vd[HEADS][HDIM];
__device__ float2 g_vs[HEADS][HDIM];
__device__ float4 g_sd[NN];
__device__ float4 g_ss[NN];
__device__ float  g_badj[NN];            // act_j ? 0.15*sum(ss_j) : -inf
__device__ int    g_cur[NN];
__device__ ulonglong2 g_edge[NN * CAP];  // .x = (pos<<32)|float_bits(w), .y = col
__device__ int    g_is_byte;
__device__ unsigned g_tick;              // global barrier ticket (reset at exit)
__device__ unsigned g_exit;              // exit counter (reset at exit)

// ---------------- double-single helper ----------------
__device__ __forceinline__ void dsadd(float& s, float& c, float p, float pe) {
    float t = s + p;
    float z = t - s;
    float e = (s - (t - z)) + (p - z);
    s = t;
    c += e + pe;
}

// global barrier #gen (1-based): wait until gen*GRID arrivals this launch
__device__ __forceinline__ void gbar(int gen) {
    __syncthreads();
    if (threadIdx.x == 0) {
        __threadfence();
        atomicAdd(&g_tick, 1u);
        unsigned target = (unsigned)gen * GRID;
        while (*(volatile unsigned*)&g_tick < target) { }
    }
    __syncthreads();
}

// warp-collective (warp 0): largest bin B with suffix-count >= K
__device__ __forceinline__ void scan_hist(const int* __restrict__ hist, int K,
                                          int* outB, int* outAbove) {
    int lane = threadIdx.x & 31;
    int base = lane * 8;
    int h[8];
    #pragma unroll
    for (int r = 0; r < 8; r++) h[r] = hist[base + r];
    int ls[8];
    int s = 0;
    #pragma unroll
    for (int r = 7; r >= 0; r--) { s += h[r]; ls[r] = s; }
    int run = s;
    #pragma unroll
    for (int off = 1; off < 32; off <<= 1) {
        int t = __shfl_down_sync(FULLM, run, off);
        if (lane + off < 32) run += t;
    }
    int above = run - s;
    int cand = -1, candAbove = 0;
    #pragma unroll
    for (int r = 7; r >= 0; r--) {
        if (cand < 0 && above + ls[r] >= K) {
            cand = base + r;
            candAbove = above + ls[r] - h[r];
        }
    }
    int bestB = cand, bestA = candAbove;
    #pragma unroll
    for (int off = 16; off; off >>= 1) {
        int ob = __shfl_xor_sync(FULLM, bestB, off);
        int oa = __shfl_xor_sync(FULLM, bestA, off);
        if (ob > bestB) { bestB = ob; bestA = oa; }
    }
    if (lane == 0) {
        *outB = (bestB < 0) ? 0 : bestB;
        *outAbove = (bestB < 0) ? 0 : bestA;
    }
}

// ---------------- the one fused kernel ----------------
__global__ __launch_bounds__(RT, 2) void k_all(const float* __restrict__ E,
                                               const float* __restrict__ W,
                                               const float* __restrict__ att,
                                               const float* __restrict__ lambda_p,
                                               const uint8_t* __restrict__ mask,
                                               const uint8_t* __restrict__ act,
                                               const int* __restrict__ eidx,
                                               const float* __restrict__ ew,
                                               float* __restrict__ out) {
    __shared__ unsigned long long corr[NN];    // 32 KB
    __shared__ unsigned long long buf[BUFSZ];
    __shared__ unsigned long long s_sel[TOPK];
    __shared__ float s_ex[TOPK];
    __shared__ int hist1[256];
    __shared__ int hist2[256];
    __shared__ int s_cnt, s_B1, s_above1, s_B2, s_above2, s_byte;

    const int bid = blockIdx.x;
    const int tid = threadIdx.x;
    const int lane = tid & 31;
    const int wid = tid >> 5;

    // ================= PHASE A: detect + zero g_cur + fold =================
    {
        int gi = bid * RT + tid;
        if (gi < NN) g_cur[gi] = 0;          // blocks 0..7 cover 4096

        if (bid == 8 || bid == 9) {          // fold: 1024 (h,k) pairs
            int pr = (bid - 8) * RT + tid;   // 0..1023
            int h = pr >> 8;
            int k = pr & 255;
            float sd = 0.f, cd = 0.f, ss = 0.f, cs = 0.f;
            #pragma unroll 8
            for (int dd = 0; dd < HD; dd++) {
                float w   = W[(h * HD + dd) * HDIM + k];
                float ad  = att[h * 2 * HD + dd];
                float as_ = att[h * 2 * HD + HD + dd];
                float p = ad * w;  float pe = fmaf(ad, w, -p);
                dsadd(sd, cd, p, pe);
                p = as_ * w;       pe = fmaf(as_, w, -p);
                dsadd(ss, cs, p, pe);
            }
            float hi = sd + cd;
            g_vd[h][k] = make_float2(hi, (sd - hi) + cd);
            hi = ss + cs;
            g_vs[h][k] = make_float2(hi, (ss - hi) + cs);
        } else if (bid == 10) {              // bool-width detection
            if (tid == 0) s_byte = 0;
            __syncthreads();
            const unsigned* mw = (const unsigned*)mask;
            for (int t = tid; t < 4096; t += RT) {
                unsigned w = mw[t];
                if (w > 1u) {
                    unsigned b0 = w & 0xFF, b1 = (w >> 8) & 0xFF,
                             b2 = (w >> 16) & 0xFF, b3 = w >> 24;
                    if (b0 <= 1u && b1 <= 1u && b2 <= 1u && b3 <= 1u) s_byte = 1;
                }
            }
            __syncthreads();
            if (tid == 0) g_is_byte = s_byte;
        }
    }
    gbar(1);

    // ================= PHASE B: sds (blocks 0..255) + scatter (256..295) ====
    if (bid < 256) {
        int g = bid * 16 + wid;              // 256*16 = 4096 rows
        const float* er = E + (size_t)g * HDIM;
        float s[8], c[8];
        #pragma unroll
        for (int a = 0; a < 8; a++) { s[a] = 0.f; c[a] = 0.f; }
        for (int k = lane; k < HDIM; k += 32) {
            float e = er[k];
            #pragma unroll
            for (int h = 0; h < HEADS; h++) {
                float2 v = g_vd[h][k];
                float p = e * v.x;
                float pe = fmaf(e, v.x, -p);
                pe = fmaf(e, v.y, pe);
                dsadd(s[h], c[h], p, pe);
                v = g_vs[h][k];
                p = e * v.x;
                pe = fmaf(e, v.x, -p);
                pe = fmaf(e, v.y, pe);
                dsadd(s[4 + h], c[4 + h], p, pe);
            }
        }
        #pragma unroll
        for (int off = 16; off; off >>= 1) {
            #pragma unroll
            for (int a = 0; a < 8; a++) {
                float os = __shfl_down_sync(FULLM, s[a], off);
                float oc = __shfl_down_sync(FULLM, c[a], off);
                float t = s[a] + os;
                float z = t - s[a];
                c[a] += oc + ((s[a] - (t - z)) + (os - z));
                s[a] = t;
            }
        }
        if (lane == 0) {
            g_sd[g] = make_float4(s[0] + c[0], s[1] + c[1], s[2] + c[2], s[3] + c[3]);
            float t0 = s[4] + c[4], t1 = s[5] + c[5], t2 = s[6] + c[6], t3 = s[7] + c[7];
            g_ss[g] = make_float4(t0, t1, t2, t3);
            bool aj = g_is_byte ? (act[g] != 0) : (((const unsigned*)act)[g] != 0u);
            g_badj[g] = aj ? 0.15f * ((t0 + t1) + (t2 + t3)) : -INFINITY;
        }
    } else {
        for (int e = (bid - 256) * RT + tid; e < EC; e += 40 * RT) {
            int r = eidx[e];
            int cc = eidx[EC + e];
            int p = atomicAdd(&g_cur[r], 1);
            if (p < CAP) {
                ulonglong2 rec;
                rec.x = ((unsigned long long)(unsigned)e << 32) |
                        (unsigned long long)__float_as_uint(ew[e]);
                rec.y = (unsigned long long)(unsigned)cc;
                g_edge[r * CAP + p] = rec;
            }
        }
    }
    gbar(2);

    // ================= PHASE C: rows (R7 body), strided =================
    const float lam = __ldg(lambda_p);
    const int is_byte = g_is_byte;

    for (int i = bid; i < NN; i += GRID) {
        // ---- zero ----
        #pragma unroll
        for (int k = 0; k < NN / RT; k++) corr[tid + k * RT] = 0ULL;
        if (tid < 256) { hist1[tid] = 0; hist2[tid] = 0; }
        else if (tid < 256 + TOPK) s_sel[tid - 256] = 0ULL;
        if (tid == RT - 1) s_cnt = 0;
        __syncthreads();

        // ---- scatter row edges (last-write-wins via max edge position) ----
        int cnt = g_cur[i];
        if (cnt > CAP) cnt = CAP;
        if (tid < cnt) {
            ulonglong2 rec = __ldg(&g_edge[i * CAP + tid]);
            atomicMax(&corr[(int)rec.y], rec.x);
        }
        __syncthreads();

        const float4 sdi = __ldg(&g_sd[i]);
        const float ci = 0.15f * ((sdi.x + sdi.y) + (sdi.z + sdi.w));
        const uint8_t*  mrow8  = mask + (size_t)i * NN;
        const unsigned* mrow32 = (const unsigned*)mask + (size_t)i * NN;
        const bool acti = is_byte ? (act[i] != 0) : (((const unsigned*)act)[i] != 0u);

        // ---- 8 keys + level-1 histogram ----
        unsigned kk[CPT];
        #pragma unroll
        for (int k = 0; k < CPT; k++) {
            int j = tid + k * RT;
            float4 ssj = __ldg(&g_ss[j]);
            float x0 = sdi.x + ssj.x;
            float x1 = sdi.y + ssj.y;
            float x2 = sdi.z + ssj.z;
            float x3 = sdi.w + ssj.w;
            float sa = fabsf(x0) + fabsf(x1);
            float sb = fabsf(x2) + fabsf(x3);
            float w = __uint_as_float((unsigned)(((const unsigned*)corr)[2 * j]));
            float a = __ldg(&g_badj[j]);
            bool mj = is_byte ? (mrow8[j] != 0) : (mrow32[j] != 0u);
            float sc = ci + fmaf(lam, w, a);
            sc = fmaf(0.1f, sa + sb, sc);
            sc = (acti && mj) ? sc : -INFINITY;
            unsigned u = __float_as_uint(sc);
            u ^= ((unsigned)(((int)u) >> 31)) | 0x80000000u;
            kk[k] = u;
        }
        #pragma unroll
        for (int k = 0; k < CPT; k++) {
            unsigned b1 = kk[k] >> 24;
            unsigned peers = __match_any_sync(FULLM, b1);
            if ((peers & ((1u << lane) - 1u)) == 0)
                atomicAdd(&hist1[b1], (int)__popc(peers));
        }
        __syncthreads();

        if (wid == 0) scan_hist(hist1, TOPK, &s_B1, &s_above1);
        __syncthreads();
        const int B1 = s_B1;
        const int above1 = s_above1;

        #pragma unroll
        for (int k = 0; k < CPT; k++) {
            if ((int)(kk[k] >> 24) == B1)
                atomicAdd(&hist2[(kk[k] >> 16) & 0xFF], 1);
        }
        __syncthreads();
        if (wid == 0) scan_hist(hist2, TOPK - above1, &s_B2, &s_above2);
        __syncthreads();
        const int B2 = s_B2;

        #pragma unroll
        for (int k = 0; k < CPT; k++) {
            int b1k = (int)(kk[k] >> 24);
            bool cand = (b1k > B1) || (b1k == B1 && (int)((kk[k] >> 16) & 0xFF) >= B2);
            if (cand) {
                int p = atomicAdd(&s_cnt, 1);
                if (p < BUFSZ) {
                    int j = tid + k * RT;
                    buf[p] = ((unsigned long long)kk[k] << 32) |
                             (unsigned long long)(0xFFFFFFFFu - (unsigned)j);
                }
            }
        }
        __syncthreads();

        // ---- rank-select top-15 ----
        int n = s_cnt < BUFSZ ? s_cnt : BUFSZ;
        if (tid < BUFSZ) {
            unsigned long long K = (tid < n) ? buf[tid] : 0ULL;
            int rank = 0;
            for (int s = 0; s < n; s++) rank += (buf[s] > K);
            if (tid < n && rank < TOPK) s_sel[rank] = K;
        }
        __syncthreads();

        // ---- decode + softmax + write ----
        if (tid < TOPK) {
            unsigned long long k64 = s_sel[tid];
            unsigned u = (unsigned)(k64 >> 32);
            float v = (u & 0x80000000u) ? __uint_as_float(u ^ 0x80000000u)
                                        : __uint_as_float(~u);
            unsigned j = 0xFFFFFFFFu - (unsigned)(k64 & 0xFFFFFFFFu);

            unsigned u0 = (unsigned)(s_sel[0] >> 32);
            float v0 = (u0 & 0x80000000u) ? __uint_as_float(u0 ^ 0x80000000u)
                                          : __uint_as_float(~u0);
            s_ex[tid] = expf(v - v0);

            out[(size_t)i * TOPK + tid] = (float)j;
            out[(size_t)NN * TOPK + (size_t)i * TOPK + tid] = (float)i;
        }
        __syncthreads();
        if (tid < TOPK) {
            float sum = 0.f;
            #pragma unroll
            for (int r = 0; r < TOPK; r++) sum += s_ex[r];
            out[2 * (size_t)NN * TOPK + (size_t)i * TOPK + tid] = s_ex[tid] / sum;
        }
        __syncthreads();
    }

    // ================= epilogue: reset barrier counters =================
    __syncthreads();
    if (tid == 0) {
        __threadfence();
        unsigned t = atomicAdd(&g_exit, 1u);
        if (t == GRID - 1) {        // last block out resets for next replay
            g_tick = 0;
            g_exit = 0;
            __threadfence();
        }
    }
}

// ---------------- launcher: ONE kernel ----------------
extern "C" void kernel_launch(void* const* d_in, const int* in_sizes, int n_in,
                              void* d_out, int out_size) {
    const float*   emb  = (const float*)d_in[0];
    const float*   W    = (const float*)d_in[1];
    const float*   att  = (const float*)d_in[2];
    const float*   lam  = (const float*)d_in[3];
    const uint8_t* mask = (const uint8_t*)d_in[4];
    const uint8_t* act  = (const uint8_t*)d_in[5];
    const int*     eidx = (const int*)d_in[6];
    const float*   ew   = (const float*)d_in[7];
    float* out = (float*)d_out;

    k_all<<<GRID, RT>>>(emb, W, att, lam, mask, act, eidx, ew, out);
}

// round 12
// speedup vs baseline: 1.2427x; 1.0828x over previous
#include <cuda_runtime.h>
#include <cstdint>
#include <math.h>

#define NN     4096
#define HDIM   256
#define HEADS  4
#define HD     64
#define EC     131072
#define TOPK   15
#define CAP    160
#define RT     256      // threads per block
#define CPT    16       // candidates per thread = NN / RT
#define BUFSZ  256
#define GRID   592      // 4 blocks/SM on 148 SMs -> all co-resident
#define FULLM  0xffffffffu

// ---------------- device scratch ----------------
__device__ float2 g_vd[HEADS][HDIM];
__device__ float2 g_vs[HEADS][HDIM];
__device__ float4 g_sd[NN];
__device__ float4 g_ss[NN];
__device__ float  g_badj[NN];            // act_j ? 0.15*sum(ss_j) : -inf
__device__ int    g_cur[NN];
__device__ ulonglong2 g_edge[NN * CAP];  // .x = (pos<<32)|float_bits(w), .y = col
__device__ int    g_is_byte;
__device__ unsigned g_tick;
__device__ unsigned g_exit;

// ---------------- dynamic smem ----------------
struct CSmem {
    unsigned long long corr[NN];     // 32 KB
    unsigned           kk[NN];       // 16 KB staged keys
    unsigned long long buf[BUFSZ];   // 2 KB
    unsigned long long sel[TOPK];
    int  hist1[256];
    int  hist2[256];
    int  cnt, B1, above1, B2, above2, sbyte;
};

// ---------------- double-single helper ----------------
__device__ __forceinline__ void dsadd(float& s, float& c, float p, float pe) {
    float t = s + p;
    float z = t - s;
    float e = (s - (t - z)) + (p - z);
    s = t;
    c += e + pe;
}

// global barrier #gen (1-based)
__device__ __forceinline__ void gbar(int gen) {
    __syncthreads();
    if (threadIdx.x == 0) {
        __threadfence();
        atomicAdd(&g_tick, 1u);
        unsigned target = (unsigned)gen * GRID;
        while (*(volatile unsigned*)&g_tick < target) { }
    }
    __syncthreads();
}

// warp-collective (warp 0): largest bin B with suffix-count >= K
__device__ __forceinline__ void scan_hist(const int* __restrict__ hist, int K,
                                          int* outB, int* outAbove) {
    int lane = threadIdx.x & 31;
    int base = lane * 8;
    int h[8];
    #pragma unroll
    for (int r = 0; r < 8; r++) h[r] = hist[base + r];
    int ls[8];
    int s = 0;
    #pragma unroll
    for (int r = 7; r >= 0; r--) { s += h[r]; ls[r] = s; }
    int run = s;
    #pragma unroll
    for (int off = 1; off < 32; off <<= 1) {
        int t = __shfl_down_sync(FULLM, run, off);
        if (lane + off < 32) run += t;
    }
    int above = run - s;
    int cand = -1, candAbove = 0;
    #pragma unroll
    for (int r = 7; r >= 0; r--) {
        if (cand < 0 && above + ls[r] >= K) {
            cand = base + r;
            candAbove = above + ls[r] - h[r];
        }
    }
    int bestB = cand, bestA = candAbove;
    #pragma unroll
    for (int off = 16; off; off >>= 1) {
        int ob = __shfl_xor_sync(FULLM, bestB, off);
        int oa = __shfl_xor_sync(FULLM, bestA, off);
        if (ob > bestB) { bestB = ob; bestA = oa; }
    }
    if (lane == 0) {
        *outB = (bestB < 0) ? 0 : bestB;
        *outAbove = (bestB < 0) ? 0 : bestA;
    }
}

// ---------------- the one fused kernel ----------------
__global__ __launch_bounds__(RT, 4) void k_all(const float* __restrict__ E,
                                               const float* __restrict__ W,
                                               const float* __restrict__ att,
                                               const float* __restrict__ lambda_p,
                                               const uint8_t* __restrict__ mask,
                                               const uint8_t* __restrict__ act,
                                               const int* __restrict__ eidx,
                                               const float* __restrict__ ew,
                                               float* __restrict__ out) {
    extern __shared__ CSmem smem[];
    CSmem* S = smem;

    const int bid = blockIdx.x;
    const int tid = threadIdx.x;
    const int lane = tid & 31;
    const int wid = tid >> 5;

    // ================= PHASE A =================
    if (bid < 16) {
        g_cur[bid * RT + tid] = 0;
    } else if (bid < 20) {
        int pr = (bid - 16) * RT + tid;   // 0..1023
        int h = pr >> 8;
        int k = pr & 255;
        float sd = 0.f, cd = 0.f, ss = 0.f, cs = 0.f;
        #pragma unroll 8
        for (int dd = 0; dd < HD; dd++) {
            float w   = W[(h * HD + dd) * HDIM + k];
            float ad  = att[h * 2 * HD + dd];
            float as_ = att[h * 2 * HD + HD + dd];
            float p = ad * w;  float pe = fmaf(ad, w, -p);
            dsadd(sd, cd, p, pe);
            p = as_ * w;       pe = fmaf(as_, w, -p);
            dsadd(ss, cs, p, pe);
        }
        float hi = sd + cd;
        g_vd[h][k] = make_float2(hi, (sd - hi) + cd);
        hi = ss + cs;
        g_vs[h][k] = make_float2(hi, (ss - hi) + cs);
    } else if (bid == 20) {
        if (tid == 0) S->sbyte = 0;
        __syncthreads();
        const unsigned* mw = (const unsigned*)mask;
        for (int t = tid; t < 4096; t += RT) {
            unsigned w = mw[t];
            if (w > 1u) {
                unsigned b0 = w & 0xFF, b1 = (w >> 8) & 0xFF,
                         b2 = (w >> 16) & 0xFF, b3 = w >> 24;
                if (b0 <= 1u && b1 <= 1u && b2 <= 1u && b3 <= 1u) S->sbyte = 1;
            }
        }
        __syncthreads();
        if (tid == 0) g_is_byte = S->sbyte;
    }
    gbar(1);

    // ================= PHASE B: sds (0..511) + scatter (512..591) ==========
    if (bid < 512) {
        int g = bid * 8 + wid;
        const float* er = E + (size_t)g * HDIM;
        float s[8], c[8];
        #pragma unroll
        for (int a = 0; a < 8; a++) { s[a] = 0.f; c[a] = 0.f; }
        for (int k = lane; k < HDIM; k += 32) {
            float e = er[k];
            #pragma unroll
            for (int h = 0; h < HEADS; h++) {
                float2 v = g_vd[h][k];
                float p = e * v.x;
                float pe = fmaf(e, v.x, -p);
                pe = fmaf(e, v.y, pe);
                dsadd(s[h], c[h], p, pe);
                v = g_vs[h][k];
                p = e * v.x;
                pe = fmaf(e, v.x, -p);
                pe = fmaf(e, v.y, pe);
                dsadd(s[4 + h], c[4 + h], p, pe);
            }
        }
        #pragma unroll
        for (int off = 16; off; off >>= 1) {
            #pragma unroll
            for (int a = 0; a < 8; a++) {
                float os = __shfl_down_sync(FULLM, s[a], off);
                float oc = __shfl_down_sync(FULLM, c[a], off);
                float t = s[a] + os;
                float z = t - s[a];
                c[a] += oc + ((s[a] - (t - z)) + (os - z));
                s[a] = t;
            }
        }
        if (lane == 0) {
            g_sd[g] = make_float4(s[0] + c[0], s[1] + c[1], s[2] + c[2], s[3] + c[3]);
            float t0 = s[4] + c[4], t1 = s[5] + c[5], t2 = s[6] + c[6], t3 = s[7] + c[7];
            g_ss[g] = make_float4(t0, t1, t2, t3);
            bool aj = g_is_byte ? (act[g] != 0) : (((const unsigned*)act)[g] != 0u);
            g_badj[g] = aj ? 0.15f * ((t0 + t1) + (t2 + t3)) : -INFINITY;
        }
    } else {
        for (int e = (bid - 512) * RT + tid; e < EC; e += 80 * RT) {
            int r = eidx[e];
            int cc = eidx[EC + e];
            int p = atomicAdd(&g_cur[r], 1);
            if (p < CAP) {
                ulonglong2 rec;
                rec.x = ((unsigned long long)(unsigned)e << 32) |
                        (unsigned long long)__float_as_uint(ew[e]);
                rec.y = (unsigned long long)(unsigned)cc;
                g_edge[r * CAP + p] = rec;
            }
        }
    }
    // zero this block's corr table once (maintained incrementally afterward)
    #pragma unroll
    for (int k = 0; k < NN / RT; k++) S->corr[tid + k * RT] = 0ULL;
    gbar(2);

    // ================= PHASE C: rows, 4 independent blocks per SM ==========
    const float lam = __ldg(lambda_p);
    const int is_byte = g_is_byte;

    for (int i = bid; i < NN; i += GRID) {
        // ---- P1: row init + edge scatter (corr already zeroed) ----
        S->hist1[tid] = 0;
        S->hist2[tid] = 0;
        if (tid < TOPK) S->sel[tid] = 0ULL;
        if (tid == RT - 1) S->cnt = 0;
        int cnt = g_cur[i];
        if (cnt > CAP) cnt = CAP;
        if (tid < cnt) {
            ulonglong2 rec = __ldg(&g_edge[i * CAP + tid]);
            atomicMax(&S->corr[(int)rec.y], rec.x);
        }
        __syncthreads();

        const float4 sdi = __ldg(&g_sd[i]);
        const float ci = 0.15f * ((sdi.x + sdi.y) + (sdi.z + sdi.w));
        const uint8_t*  mrow8  = mask + (size_t)i * NN;
        const unsigned* mrow32 = (const unsigned*)mask + (size_t)i * NN;
        const bool acti = is_byte ? (act[i] != 0) : (((const unsigned*)act)[i] != 0u);

        // ---- P2: compute 16 keys -> smem + level-1 histogram ----
        #pragma unroll 8
        for (int k = 0; k < CPT; k++) {
            int j = tid + k * RT;
            float4 ssj = __ldg(&g_ss[j]);
            float x0 = sdi.x + ssj.x;
            float x1 = sdi.y + ssj.y;
            float x2 = sdi.z + ssj.z;
            float x3 = sdi.w + ssj.w;
            float sa = fabsf(x0) + fabsf(x1);
            float sb = fabsf(x2) + fabsf(x3);
            float w = __uint_as_float((unsigned)(((const unsigned*)S->corr)[2 * j]));
            float a = __ldg(&g_badj[j]);
            bool mj = is_byte ? (mrow8[j] != 0) : (mrow32[j] != 0u);
            float sc = ci + fmaf(lam, w, a);
            sc = fmaf(0.1f, sa + sb, sc);
            sc = (acti && mj) ? sc : -INFINITY;
            unsigned u = __float_as_uint(sc);
            u ^= ((unsigned)(((int)u) >> 31)) | 0x80000000u;
            S->kk[j] = u;
            unsigned b1 = u >> 24;
            unsigned peers = __match_any_sync(FULLM, b1);
            if ((peers & ((1u << lane) - 1u)) == 0)
                atomicAdd(&S->hist1[b1], (int)__popc(peers));
        }
        __syncthreads();

        // ---- P3: warp0 scans level-1; warps 1..7 un-zero corr for next row --
        if (wid == 0) {
            scan_hist(S->hist1, TOPK, &S->B1, &S->above1);
        } else {
            for (int j = tid - 32; j < NN; j += RT - 32) S->corr[j] = 0ULL;
        }
        __syncthreads();
        const int B1 = S->B1;
        const int above1 = S->above1;

        // ---- P4: level-2 histogram ----
        #pragma unroll 8
        for (int k = 0; k < CPT; k++) {
            unsigned u = S->kk[tid + k * RT];
            if ((int)(u >> 24) == B1)
                atomicAdd(&S->hist2[(u >> 16) & 0xFF], 1);
        }
        __syncthreads();

        // ---- P5: level-2 scan ----
        if (wid == 0) scan_hist(S->hist2, TOPK - above1, &S->B2, &S->above2);
        __syncthreads();
        const int B2 = S->B2;

        // ---- P6: append candidates ----
        #pragma unroll 8
        for (int k = 0; k < CPT; k++) {
            int j = tid + k * RT;
            unsigned u = S->kk[j];
            int b1k = (int)(u >> 24);
            bool cand = (b1k > B1) || (b1k == B1 && (int)((u >> 16) & 0xFF) >= B2);
            if (cand) {
                int p = atomicAdd(&S->cnt, 1);
                if (p < BUFSZ) {
                    S->buf[p] = ((unsigned long long)u << 32) |
                                (unsigned long long)(0xFFFFFFFFu - (unsigned)j);
                }
            }
        }
        __syncthreads();

        // ---- P7: rank-select top-15 ----
        int n = S->cnt < BUFSZ ? S->cnt : BUFSZ;
        {
            unsigned long long K = (tid < n) ? S->buf[tid] : 0ULL;
            int rank = 0;
            for (int s = 0; s < n; s++) rank += (S->buf[s] > K);
            if (tid < n && rank < TOPK) S->sel[rank] = K;
        }
        __syncthreads();

        // ---- P8: warp0 decode + softmax + write ----
        if (wid == 0) {
            unsigned long long k64 = (lane < TOPK) ? S->sel[lane] : 0ULL;
            unsigned u = (unsigned)(k64 >> 32);
            float v = (u & 0x80000000u) ? __uint_as_float(u ^ 0x80000000u)
                                        : __uint_as_float(~u);
            unsigned j = 0xFFFFFFFFu - (unsigned)(k64 & 0xFFFFFFFFu);
            float v0 = __shfl_sync(FULLM, v, 0);
            float e = (lane < TOPK) ? expf(v - v0) : 0.f;
            float s = e;
            #pragma unroll
            for (int off = 16; off; off >>= 1) s += __shfl_xor_sync(FULLM, s, off);
            if (lane < TOPK) {
                out[(size_t)i * TOPK + lane] = (float)j;
                out[(size_t)NN * TOPK + (size_t)i * TOPK + lane] = (float)i;
                out[2 * (size_t)NN * TOPK + (size_t)i * TOPK + lane] = e / s;
            }
        }
        __syncthreads();
    }

    // ================= epilogue: reset barrier counters =================
    if (tid == 0) {
        __threadfence();
        unsigned t = atomicAdd(&g_exit, 1u);
        if (t == GRID - 1) {
            g_tick = 0;
            g_exit = 0;
            __threadfence();
        }
    }
}

// ---------------- launcher ----------------
extern "C" void kernel_launch(void* const* d_in, const int* in_sizes, int n_in,
                              void* d_out, int out_size) {
    const float*   emb  = (const float*)d_in[0];
    const float*   W    = (const float*)d_in[1];
    const float*   att  = (const float*)d_in[2];
    const float*   lam  = (const float*)d_in[3];
    const uint8_t* mask = (const uint8_t*)d_in[4];
    const uint8_t* act  = (const uint8_t*)d_in[5];
    const int*     eidx = (const int*)d_in[6];
    const float*   ew   = (const float*)d_in[7];
    float* out = (float*)d_out;

    cudaFuncSetAttribute(k_all, cudaFuncAttributeMaxDynamicSharedMemorySize,
                         (int)sizeof(CSmem));
    k_all<<<GRID, RT, sizeof(CSmem)>>>(emb, W, att, lam, mask, act, eidx, ew, out);
}